// round 5
// baseline (speedup 1.0000x reference)
#include <cuda_runtime.h>
#include <cuda_bf16.h>
#include <math.h>
#include <cstdint>

// Problem constants (fixed-shape problem)
#define N_TOK_MAX 11136
#define IN_DIM    256
#define E_DIM     256
#define NHEAD     8
#define HDIM      32
#define NB        16
#define QKV_DIM   768

typedef unsigned long long u64;
typedef unsigned int       u32;

// ---- f32x2 packed-math helpers (sm_103a; ptxas won't auto-fuse these) ----
__device__ __forceinline__ u64 pack2(float lo, float hi) {
    u64 d; asm("mov.b64 %0, {%1, %2};" : "=l"(d) : "f"(lo), "f"(hi)); return d;
}
__device__ __forceinline__ void unpack2(u64 d, float& lo, float& hi) {
    asm("mov.b64 {%0, %1}, %2;" : "=f"(lo), "=f"(hi) : "l"(d));
}
__device__ __forceinline__ u64 ffma2(u64 a, u64 b, u64 c) {
    u64 d; asm("fma.rn.f32x2 %0, %1, %2, %3;" : "=l"(d) : "l"(a), "l"(b), "l"(c));
    return d;
}
__device__ __forceinline__ u64 mul2(u64 a, u64 b) {
    u64 d; asm("mul.rn.f32x2 %0, %1, %2;" : "=l"(d) : "l"(a), "l"(b)); return d;
}
// 16B shared load into two packed f32x2 (requires 16B-aligned address)
__device__ __forceinline__ void lds_2x64(u64& a, u64& b, u32 addr) {
    asm volatile("ld.shared.v2.b64 {%0, %1}, [%2];" : "=l"(a), "=l"(b) : "r"(addr));
}
__device__ __forceinline__ u32 sm32(const void* p) {
    return (u32)__cvta_generic_to_shared(p);
}

// QKV layout per reference: reshape(B,S,8,96) then split ->
//   head h: q = cols [96h, 96h+32), k = [96h+32, 96h+64), v = [96h+64, 96h+96)

// Scratch (device globals: allocation-free rule)
__device__ float g_qkv[(size_t)N_TOK_MAX * QKV_DIM];   // [N, 768]
__device__ float g_att[(size_t)N_TOK_MAX * E_DIM];     // [N, 256] attention out
__device__ int   g_start[NB + 1];

// ---------------------------------------------------------------------------
// Kernel 1: histogram of sorted batch ids -> segment start offsets
// ---------------------------------------------------------------------------
__global__ void hist_kernel(const int* __restrict__ ids, int n) {
    __shared__ int cnt[NB];
    int t = threadIdx.x;
    if (t < NB) cnt[t] = 0;
    __syncthreads();
    for (int i = t; i < n; i += blockDim.x)
        atomicAdd(&cnt[ids[i]], 1);
    __syncthreads();
    if (t == 0) {
        int acc = 0;
        for (int v = 0; v < NB; v++) { g_start[v] = acc; acc += cnt[v]; }
        g_start[NB] = acc;
    }
}

// ---------------------------------------------------------------------------
// Tiled SGEMM with f32x2: C[M,N] = A[M,K] @ B[N,K]^T + bias[N]
// BM=64 BN=64 BK=16, 128 threads, per-thread 8x4 tile as 4 row-pairs x 4 cols.
// ---------------------------------------------------------------------------
#define BM 64
#define BN 64
#define BK 16

__device__ __forceinline__ void gemm_body(const float* __restrict__ A,
                                          const float* __restrict__ B,
                                          const float* __restrict__ bias,
                                          float* __restrict__ C,
                                          int M, int N, int K) {
    __shared__ float As[BK][BM + 4];   // stride 68 floats = 272B (16B aligned)
    __shared__ float Bs[BK][BN + 4];
    int t  = threadIdx.x;            // 0..127
    int m0 = blockIdx.y * BM;
    int n0 = blockIdx.x * BN;
    int tn = t & 15;                 // cols tn*4..+4
    int tm = t >> 4;                 // row-pairs tm*8 + 2ip

    const u32 asBase = sm32(&As[0][0]);

    u64 acc[4][4];
#pragma unroll
    for (int i = 0; i < 4; i++)
#pragma unroll
        for (int j = 0; j < 4; j++) acc[i][j] = 0ull;

    for (int k0 = 0; k0 < K; k0 += BK) {
        // load A tile (64x16) as float4, store transposed
#pragma unroll
        for (int i = 0; i < 2; i++) {
            int f   = t + i * 128;           // 0..255
            int row = f >> 2, kq = f & 3;
            int gr  = min(m0 + row, M - 1);
            float4 v = *(const float4*)(A + (size_t)gr * K + k0 + kq * 4);
            As[kq * 4 + 0][row] = v.x; As[kq * 4 + 1][row] = v.y;
            As[kq * 4 + 2][row] = v.z; As[kq * 4 + 3][row] = v.w;
        }
        // load B tile (64x16), store transposed
#pragma unroll
        for (int i = 0; i < 2; i++) {
            int f   = t + i * 128;
            int row = f >> 2, kq = f & 3;
            float4 v = *(const float4*)(B + (size_t)(n0 + row) * K + k0 + kq * 4);
            Bs[kq * 4 + 0][row] = v.x; Bs[kq * 4 + 1][row] = v.y;
            Bs[kq * 4 + 2][row] = v.z; Bs[kq * 4 + 3][row] = v.w;
        }
        __syncthreads();
#pragma unroll
        for (int k = 0; k < BK; k++) {
            u64 a01, a23, a45, a67;
            u32 aa = asBase + (u32)(k * (BM + 4) + tm * 8) * 4u;
            lds_2x64(a01, a23, aa);
            lds_2x64(a45, a67, aa + 16u);
            float b0 = Bs[k][tn * 4 + 0];
            float b1 = Bs[k][tn * 4 + 1];
            float b2 = Bs[k][tn * 4 + 2];
            float b3 = Bs[k][tn * 4 + 3];
            u64 bd0 = pack2(b0, b0), bd1 = pack2(b1, b1);
            u64 bd2 = pack2(b2, b2), bd3 = pack2(b3, b3);
            acc[0][0] = ffma2(a01, bd0, acc[0][0]);
            acc[1][0] = ffma2(a23, bd0, acc[1][0]);
            acc[2][0] = ffma2(a45, bd0, acc[2][0]);
            acc[3][0] = ffma2(a67, bd0, acc[3][0]);
            acc[0][1] = ffma2(a01, bd1, acc[0][1]);
            acc[1][1] = ffma2(a23, bd1, acc[1][1]);
            acc[2][1] = ffma2(a45, bd1, acc[2][1]);
            acc[3][1] = ffma2(a67, bd1, acc[3][1]);
            acc[0][2] = ffma2(a01, bd2, acc[0][2]);
            acc[1][2] = ffma2(a23, bd2, acc[1][2]);
            acc[2][2] = ffma2(a45, bd2, acc[2][2]);
            acc[3][2] = ffma2(a67, bd2, acc[3][2]);
            acc[0][3] = ffma2(a01, bd3, acc[0][3]);
            acc[1][3] = ffma2(a23, bd3, acc[1][3]);
            acc[2][3] = ffma2(a45, bd3, acc[2][3]);
            acc[3][3] = ffma2(a67, bd3, acc[3][3]);
        }
        __syncthreads();
    }

#pragma unroll
    for (int ip = 0; ip < 4; ip++) {
        int m = m0 + tm * 8 + 2 * ip;
#pragma unroll
        for (int j = 0; j < 4; j++) {
            int nn = n0 + tn * 4 + j;
            float lo, hi;
            unpack2(acc[ip][j], lo, hi);
            float bb = bias[nn];
            if (m < M)     C[(size_t)m * N + nn]       = lo + bb;
            if (m + 1 < M) C[(size_t)(m + 1) * N + nn] = hi + bb;
        }
    }
}

__global__ void qkv_gemm_kernel(const float* __restrict__ x,
                                const float* __restrict__ w,
                                const float* __restrict__ b, int n) {
    gemm_body(x, w, b, g_qkv, n, QKV_DIM, IN_DIM);
}

__global__ void proj_gemm_kernel(const float* __restrict__ w,
                                 const float* __restrict__ b,
                                 float* __restrict__ out, int n) {
    gemm_body(g_att, w, b, out, n, E_DIM, E_DIM);
}

// ---------------------------------------------------------------------------
// Kernel 3: varlen flash attention, fp32 + f32x2.
// Block = (64-query tile of one segment, one head). 256 threads (8 warps).
// Thread t: rg = t>>3 -> query rows {2rg, 2rg+1}; cg = t&7.
//   QK: 8 key cols at kc0=8cg (4 packed pairs). PV: 4 hd cols at vc0=4cg (2 pairs).
// ---------------------------------------------------------------------------
__global__ __launch_bounds__(256) void attn_kernel(int n) {
    const int seg = blockIdx.y;
    const int h   = blockIdx.z;
    const int qs  = g_start[seg];
    const int qe  = g_start[seg + 1];
    const int q0  = qs + blockIdx.x * 64;
    if (q0 >= qe) return;

    __shared__ float Qt[HDIM][68];    // dim-major Q   (stride 272B, 16B aligned)
    __shared__ float Kt[HDIM][68];    // dim-major K
    __shared__ float Vs[64][36];      // key-major V   (stride 144B, 16B aligned)
    __shared__ float St[64][66];      // key-major probs, packed row-pairs

    const int t = threadIdx.x;
    const float* __restrict__ qkv = g_qkv;
    const int qoff = h * 96;
    const int koff = h * 96 + 32;
    const int voff = h * 96 + 64;

    // cooperative Q load (transposed): row = t>>2, 8 dims at (t&3)*8
    {
        int r = t >> 2, c8 = (t & 3) * 8;
        int row = min(q0 + r, n - 1);
        const float* p = qkv + (size_t)row * QKV_DIM + qoff + c8;
        float4 v0 = *(const float4*)p;
        float4 v1 = *(const float4*)(p + 4);
        Qt[c8 + 0][r] = v0.x; Qt[c8 + 1][r] = v0.y;
        Qt[c8 + 2][r] = v0.z; Qt[c8 + 3][r] = v0.w;
        Qt[c8 + 4][r] = v1.x; Qt[c8 + 5][r] = v1.y;
        Qt[c8 + 6][r] = v1.z; Qt[c8 + 7][r] = v1.w;
    }
    __syncthreads();

    const int rg  = t >> 3;       // 0..31
    const int cg  = t & 7;        // 0..7
    const int r0  = rg * 2;
    const int kc0 = cg * 8;
    const int vc0 = cg * 4;

    const u32 ktBase = sm32(&Kt[0][0]);
    const u32 vsBase = sm32(&Vs[0][0]);

    float m0 = -1e30f, m1 = -1e30f;
    float l0 = 0.f, l1 = 0.f;
    u64 o2[2][2] = {{0ull, 0ull}, {0ull, 0ull}};
    const float scale = 0.17677669529663687f;   // 1/sqrt(32)

    for (int j0 = qs; j0 < qe; j0 += 64) {
        const int nk = min(64, qe - j0);
        // K (transposed) + V (direct) chunk load
        {
            int r = t >> 2, c8 = (t & 3) * 8;
            int row = min(j0 + r, n - 1);
            const float* kp = qkv + (size_t)row * QKV_DIM + koff + c8;
            const float* vp = qkv + (size_t)row * QKV_DIM + voff + c8;
            float4 k0 = *(const float4*)kp;
            float4 k1 = *(const float4*)(kp + 4);
            Kt[c8 + 0][r] = k0.x; Kt[c8 + 1][r] = k0.y;
            Kt[c8 + 2][r] = k0.z; Kt[c8 + 3][r] = k0.w;
            Kt[c8 + 4][r] = k1.x; Kt[c8 + 5][r] = k1.y;
            Kt[c8 + 6][r] = k1.z; Kt[c8 + 7][r] = k1.w;
            *(float4*)&Vs[r][c8]     = *(const float4*)vp;
            *(float4*)&Vs[r][c8 + 4] = *(const float4*)(vp + 4);
        }
        __syncthreads();

        // ---- QK^T: acc[row r][key-pair cp] packed over key pairs ----
        u64 acc[2][4];
#pragma unroll
        for (int r = 0; r < 2; r++)
#pragma unroll
            for (int cp = 0; cp < 4; cp++) acc[r][cp] = 0ull;

#pragma unroll
        for (int k = 0; k < HDIM; k++) {
            float qa = Qt[k][r0];
            float qb = Qt[k][r0 + 1];
            u64 qd0 = pack2(qa, qa);
            u64 qd1 = pack2(qb, qb);
            u64 k01, k23, k45, k67;
            u32 ka = ktBase + (u32)(k * 68 + kc0) * 4u;
            lds_2x64(k01, k23, ka);
            lds_2x64(k45, k67, ka + 16u);
            acc[0][0] = ffma2(k01, qd0, acc[0][0]);
            acc[0][1] = ffma2(k23, qd0, acc[0][1]);
            acc[0][2] = ffma2(k45, qd0, acc[0][2]);
            acc[0][3] = ffma2(k67, qd0, acc[0][3]);
            acc[1][0] = ffma2(k01, qd1, acc[1][0]);
            acc[1][1] = ffma2(k23, qd1, acc[1][1]);
            acc[1][2] = ffma2(k45, qd1, acc[1][2]);
            acc[1][3] = ffma2(k67, qd1, acc[1][3]);
        }

        float s0[8], s1[8];
#pragma unroll
        for (int cp = 0; cp < 4; cp++) {
            unpack2(acc[0][cp], s0[2 * cp], s0[2 * cp + 1]);
            unpack2(acc[1][cp], s1[2 * cp], s1[2 * cp + 1]);
        }
#pragma unroll
        for (int c = 0; c < 8; c++) {
            bool ok = (kc0 + c) < nk;
            s0[c] = ok ? s0[c] * scale : -1e30f;
            s1[c] = ok ? s1[c] * scale : -1e30f;
        }

        // row max (8 threads/row: xor 1,2,4)
        float mc0 = s0[0], mc1 = s1[0];
#pragma unroll
        for (int c = 1; c < 8; c++) { mc0 = fmaxf(mc0, s0[c]); mc1 = fmaxf(mc1, s1[c]); }
#pragma unroll
        for (int d = 1; d <= 4; d <<= 1) {
            mc0 = fmaxf(mc0, __shfl_xor_sync(0xffffffffu, mc0, d));
            mc1 = fmaxf(mc1, __shfl_xor_sync(0xffffffffu, mc1, d));
        }
        float mn0 = fmaxf(m0, mc0);
        float mn1 = fmaxf(m1, mc1);
        float sf0 = __expf(m0 - mn0);
        float sf1 = __expf(m1 - mn1);
        m0 = mn0; m1 = mn1;

        float ls0 = 0.f, ls1 = 0.f;
#pragma unroll
        for (int c = 0; c < 8; c++) {
            float p0 = __expf(s0[c] - mn0);   // masked -> exactly 0
            float p1 = __expf(s1[c] - mn1);
            ls0 += p0; ls1 += p1;
            // packed row-pair store (8B aligned: r0 even, stride 66 even)
            *(u64*)&St[kc0 + c][r0] = pack2(p0, p1);
        }
#pragma unroll
        for (int d = 1; d <= 4; d <<= 1) {
            ls0 += __shfl_xor_sync(0xffffffffu, ls0, d);
            ls1 += __shfl_xor_sync(0xffffffffu, ls1, d);
        }
        l0 = l0 * sf0 + ls0;
        l1 = l1 * sf1 + ls1;
        {
            u64 sp0 = pack2(sf0, sf0), sp1 = pack2(sf1, sf1);
            o2[0][0] = mul2(o2[0][0], sp0);
            o2[0][1] = mul2(o2[0][1], sp0);
            o2[1][0] = mul2(o2[1][0], sp1);
            o2[1][1] = mul2(o2[1][1], sp1);
        }
        __syncthreads();   // St fully written

        // ---- P @ V: a = packed V dim-pair, b = prob duplicated ----
#pragma unroll
        for (int j = 0; j < 64; j++) {
            u64 pp = *(const u64*)&St[j][r0];
            float p0, p1;
            unpack2(pp, p0, p1);
            u64 pd0 = pack2(p0, p0);
            u64 pd1 = pack2(p1, p1);
            u64 v01, v23;
            lds_2x64(v01, v23, vsBase + (u32)(j * 36 + vc0) * 4u);
            o2[0][0] = ffma2(v01, pd0, o2[0][0]);
            o2[0][1] = ffma2(v23, pd0, o2[0][1]);
            o2[1][0] = ffma2(v01, pd1, o2[1][0]);
            o2[1][1] = ffma2(v23, pd1, o2[1][1]);
        }
        __syncthreads();   // before K/V/St reuse
    }

    float inv0 = 1.0f / l0;
    float inv1 = 1.0f / l1;
    // attention output layout: [N, H*32]
    if (q0 + r0 < qe) {
        float a, b, c, d;
        unpack2(o2[0][0], a, b);
        unpack2(o2[0][1], c, d);
        float* p = g_att + (size_t)(q0 + r0) * E_DIM + h * HDIM + vc0;
        p[0] = a * inv0; p[1] = b * inv0; p[2] = c * inv0; p[3] = d * inv0;
    }
    if (q0 + r0 + 1 < qe) {
        float a, b, c, d;
        unpack2(o2[1][0], a, b);
        unpack2(o2[1][1], c, d);
        float* p = g_att + (size_t)(q0 + r0 + 1) * E_DIM + h * HDIM + vc0;
        p[0] = a * inv1; p[1] = b * inv1; p[2] = c * inv1; p[3] = d * inv1;
    }
}

// ---------------------------------------------------------------------------
extern "C" void kernel_launch(void* const* d_in, const int* in_sizes, int n_in,
                              void* d_out, int out_size) {
    const float* x      = (const float*)d_in[0];
    const int*   ids    = (const int*)  d_in[1];
    const float* qkv_w  = (const float*)d_in[2];
    const float* qkv_b  = (const float*)d_in[3];
    const float* o_w    = (const float*)d_in[4];
    const float* o_b    = (const float*)d_in[5];
    float*       out    = (float*)d_out;
    const int n = in_sizes[1];   // token count

    hist_kernel<<<1, 256>>>(ids, n);

    dim3 g_qkvgrid(QKV_DIM / BN, (n + BM - 1) / BM);
    qkv_gemm_kernel<<<g_qkvgrid, 128>>>(x, qkv_w, qkv_b, n);

    dim3 g_attn((n + 63) / 64, NB, NHEAD);
    attn_kernel<<<g_attn, 256>>>(n);

    dim3 g_proj(E_DIM / BN, (n + BM - 1) / BM);
    proj_gemm_kernel<<<g_proj, 128>>>(o_w, o_b, out, n);
}

// round 6
// speedup vs baseline: 1.9058x; 1.9058x over previous
#include <cuda_runtime.h>
#include <cuda_bf16.h>
#include <math.h>
#include <cstdint>

#define N_TOK_MAX 11136
#define IN_DIM    256
#define E_DIM     256
#define NHEAD     8
#define HDIM      32
#define NB        16
#define QKV_DIM   768

typedef unsigned int u32;

// Scratch (device globals: allocation-free rule)
__device__ float g_qkv[(size_t)N_TOK_MAX * QKV_DIM];   // [N, 768]
__device__ float g_att[(size_t)N_TOK_MAX * E_DIM];     // [N, 256]
__device__ int   g_start[NB + 1];

// ---- tf32 helpers -----------------------------------------------------------
__device__ __forceinline__ void split_tf32(float v, u32& hi, u32& lo) {
    asm("cvt.rna.tf32.f32 %0, %1;" : "=r"(hi) : "f"(v));
    float r = v - __uint_as_float(hi);
    asm("cvt.rna.tf32.f32 %0, %1;" : "=r"(lo) : "f"(r));
}

// D += A(m16k8,row) * B(k8n8,col)  tf32->f32
__device__ __forceinline__ void mma8(float* c, const u32* a, u32 b0, u32 b1) {
    asm volatile(
        "mma.sync.aligned.m16n8k8.row.col.f32.tf32.tf32.f32 "
        "{%0,%1,%2,%3}, {%4,%5,%6,%7}, {%8,%9}, {%0,%1,%2,%3};"
        : "+f"(c[0]), "+f"(c[1]), "+f"(c[2]), "+f"(c[3])
        : "r"(a[0]), "r"(a[1]), "r"(a[2]), "r"(a[3]), "r"(b0), "r"(b1));
}

// 3xTF32: C += Ahi*Bhi + Ahi*Blo + Alo*Bhi
__device__ __forceinline__ void mma3(float* c, const u32* ah, const u32* al,
                                     u32 bh0, u32 bh1, u32 bl0, u32 bl1) {
    mma8(c, ah, bh0, bh1);
    mma8(c, ah, bl0, bl1);
    mma8(c, al, bh0, bh1);
}

// ---------------------------------------------------------------------------
// Kernel 1: histogram of sorted batch ids -> segment start offsets
// ---------------------------------------------------------------------------
__global__ void hist_kernel(const int* __restrict__ ids, int n) {
    __shared__ int cnt[NB];
    int t = threadIdx.x;
    if (t < NB) cnt[t] = 0;
    __syncthreads();
    for (int i = t; i < n; i += blockDim.x)
        atomicAdd(&cnt[ids[i]], 1);
    __syncthreads();
    if (t == 0) {
        int acc = 0;
        for (int v = 0; v < NB; v++) { g_start[v] = acc; acc += cnt[v]; }
        g_start[NB] = acc;
    }
}

// ---------------------------------------------------------------------------
// 3xTF32 MMA GEMM: C[M,N] = A[M,K] @ B[N,K]^T + bias[N]
// Block tile 64x64, 128 threads (4 warps; warp w -> rows 16w..16w+15).
// K consumed in chunks of 32 (4 k8-steps).
// ---------------------------------------------------------------------------
__global__ __launch_bounds__(128) void mma_gemm_kernel(
    const float* __restrict__ A, const float* __restrict__ Bw,
    const float* __restrict__ bias, float* __restrict__ C,
    int M, int N, int K)
{
    __shared__ float As[64][36];
    __shared__ float Bs[64][36];

    const int t    = threadIdx.x;
    const int lane = t & 31, w = t >> 5;
    const int g    = lane >> 2, tig = lane & 3;
    const int m0   = blockIdx.y * 64;
    const int n0   = blockIdx.x * 64;

    float acc[8][4];
#pragma unroll
    for (int i = 0; i < 8; i++)
#pragma unroll
        for (int j = 0; j < 4; j++) acc[i][j] = 0.f;

    const int lr = t >> 1, lc = (t & 1) * 16;   // loader: row, col-base (16 floats)

    for (int kc = 0; kc < K; kc += 32) {
        int ga = min(m0 + lr, M - 1);
#pragma unroll
        for (int q = 0; q < 4; q++) {
            float4 v = *(const float4*)(A + (size_t)ga * K + kc + lc + q * 4);
            *(float4*)&As[lr][lc + q * 4] = v;
        }
#pragma unroll
        for (int q = 0; q < 4; q++) {
            float4 v = *(const float4*)(Bw + (size_t)(n0 + lr) * K + kc + lc + q * 4);
            *(float4*)&Bs[lr][lc + q * 4] = v;
        }
        __syncthreads();

#pragma unroll
        for (int ks = 0; ks < 4; ks++) {
            const int k0 = ks * 8;
            u32 ah[4], al[4];
            split_tf32(As[16 * w + g][k0 + tig],         ah[0], al[0]);
            split_tf32(As[16 * w + g + 8][k0 + tig],     ah[1], al[1]);
            split_tf32(As[16 * w + g][k0 + tig + 4],     ah[2], al[2]);
            split_tf32(As[16 * w + g + 8][k0 + tig + 4], ah[3], al[3]);
#pragma unroll
            for (int nt = 0; nt < 8; nt++) {
                u32 bh0, bl0, bh1, bl1;
                split_tf32(Bs[nt * 8 + g][k0 + tig],     bh0, bl0);
                split_tf32(Bs[nt * 8 + g][k0 + tig + 4], bh1, bl1);
                mma3(acc[nt], ah, al, bh0, bh1, bl0, bl1);
            }
        }
        __syncthreads();
    }

    const int ra = m0 + 16 * w + g;
    const int rb = ra + 8;
#pragma unroll
    for (int nt = 0; nt < 8; nt++) {
        int col = n0 + nt * 8 + 2 * tig;
        float b0 = bias[col], b1 = bias[col + 1];
        if (ra < M) {
            C[(size_t)ra * N + col]     = acc[nt][0] + b0;
            C[(size_t)ra * N + col + 1] = acc[nt][1] + b1;
        }
        if (rb < M) {
            C[(size_t)rb * N + col]     = acc[nt][2] + b0;
            C[(size_t)rb * N + col + 1] = acc[nt][3] + b1;
        }
    }
}

// ---------------------------------------------------------------------------
// Kernel 3: varlen flash attention with 3xTF32 mma.
// Block = (64-query tile, segment, head). 128 threads, 4 warps.
// Warp w: query rows 16w..16w+15 (m16); keys in 64-chunks (8 n-tiles);
// PV reuses QK accumulator fragments as A-operand via even/odd V-row permute.
// ---------------------------------------------------------------------------
__global__ __launch_bounds__(128) void attn_mma_kernel(int n) {
    const int seg = blockIdx.y;
    const int h   = blockIdx.z;
    const int qs  = g_start[seg];
    const int qe  = g_start[seg + 1];
    const int q0  = qs + blockIdx.x * 64;
    if (q0 >= qe) return;

    __shared__ float Qs[64][36];
    __shared__ float Ks[64][36];
    __shared__ float Vp[64][36];   // V with rows permuted even-then-odd per 8-group

    const int t    = threadIdx.x;
    const int lane = t & 31, w = t >> 5;
    const int g    = lane >> 2, tig = lane & 3;

    const float* __restrict__ qkv = g_qkv;
    const int qoff = h * 96;
    const int koff = h * 96 + 32;
    const int voff = h * 96 + 64;

    const int lr = t >> 1, lc = (t & 1) * 16;

    // Q tile load (once)
    {
        int row = min(q0 + lr, qe - 1);
        const float* p = qkv + (size_t)row * QKV_DIM + qoff + lc;
        *(float4*)&Qs[lr][lc]      = *(const float4*)p;
        *(float4*)&Qs[lr][lc + 4]  = *(const float4*)(p + 4);
        *(float4*)&Qs[lr][lc + 8]  = *(const float4*)(p + 8);
        *(float4*)&Qs[lr][lc + 12] = *(const float4*)(p + 12);
    }

    // V row permutation within 8-group: key i -> row (i even ? i/2 : 4 + i/2)
    const int i8 = lr & 7;
    const int pr = (lr & ~7) | ((i8 & 1) ? 4 + (i8 >> 1) : (i8 >> 1));

    float m_a = -1e30f, m_b = -1e30f;
    float l_a = 0.f, l_b = 0.f;
    float out[4][4];
#pragma unroll
    for (int i = 0; i < 4; i++)
#pragma unroll
        for (int j = 0; j < 4; j++) out[i][j] = 0.f;

    const float scale = 0.17677669529663687f;   // 1/sqrt(32)

    for (int j0 = qs; j0 < qe; j0 += 64) {
        const int nk = min(64, qe - j0);
        // K + permuted-V chunk load
        {
            int row = min(j0 + lr, qe - 1);
            const float* kp = qkv + (size_t)row * QKV_DIM + koff + lc;
            const float* vp = qkv + (size_t)row * QKV_DIM + voff + lc;
            *(float4*)&Ks[lr][lc]      = *(const float4*)kp;
            *(float4*)&Ks[lr][lc + 4]  = *(const float4*)(kp + 4);
            *(float4*)&Ks[lr][lc + 8]  = *(const float4*)(kp + 8);
            *(float4*)&Ks[lr][lc + 12] = *(const float4*)(kp + 12);
            *(float4*)&Vp[pr][lc]      = *(const float4*)vp;
            *(float4*)&Vp[pr][lc + 4]  = *(const float4*)(vp + 4);
            *(float4*)&Vp[pr][lc + 8]  = *(const float4*)(vp + 8);
            *(float4*)&Vp[pr][lc + 12] = *(const float4*)(vp + 12);
        }
        __syncthreads();

        // ---- S = Q @ K^T (3xTF32), 8 key-tiles ----
        float S[8][4];
#pragma unroll
        for (int i = 0; i < 8; i++)
#pragma unroll
            for (int j = 0; j < 4; j++) S[i][j] = 0.f;

#pragma unroll
        for (int ks = 0; ks < 4; ks++) {
            const int k0 = ks * 8;
            u32 ah[4], al[4];
            split_tf32(Qs[16 * w + g][k0 + tig],         ah[0], al[0]);
            split_tf32(Qs[16 * w + g + 8][k0 + tig],     ah[1], al[1]);
            split_tf32(Qs[16 * w + g][k0 + tig + 4],     ah[2], al[2]);
            split_tf32(Qs[16 * w + g + 8][k0 + tig + 4], ah[3], al[3]);
#pragma unroll
            for (int nt = 0; nt < 8; nt++) {
                u32 bh0, bl0, bh1, bl1;
                split_tf32(Ks[nt * 8 + g][k0 + tig],     bh0, bl0);
                split_tf32(Ks[nt * 8 + g][k0 + tig + 4], bh1, bl1);
                mma3(S[nt], ah, al, bh0, bh1, bl0, bl1);
            }
        }

        // scale + key mask
#pragma unroll
        for (int nt = 0; nt < 8; nt++) {
            int c0 = nt * 8 + 2 * tig;
            bool ok0 = c0 < nk, ok1 = (c0 + 1) < nk;
            S[nt][0] = ok0 ? S[nt][0] * scale : -1e30f;
            S[nt][1] = ok1 ? S[nt][1] * scale : -1e30f;
            S[nt][2] = ok0 ? S[nt][2] * scale : -1e30f;
            S[nt][3] = ok1 ? S[nt][3] * scale : -1e30f;
        }

        // row max: row g uses S[.][0..1], row g+8 uses S[.][2..3]
        float ca = -1e30f, cb = -1e30f;
#pragma unroll
        for (int nt = 0; nt < 8; nt++) {
            ca = fmaxf(ca, fmaxf(S[nt][0], S[nt][1]));
            cb = fmaxf(cb, fmaxf(S[nt][2], S[nt][3]));
        }
#pragma unroll
        for (int d = 1; d <= 2; d <<= 1) {
            ca = fmaxf(ca, __shfl_xor_sync(0xffffffffu, ca, d));
            cb = fmaxf(cb, __shfl_xor_sync(0xffffffffu, cb, d));
        }
        float mn_a = fmaxf(m_a, ca);
        float mn_b = fmaxf(m_b, cb);
        float sf_a = __expf(m_a - mn_a);
        float sf_b = __expf(m_b - mn_b);
        m_a = mn_a; m_b = mn_b;

        // P = exp(S - m), partial row sums
        float sa = 0.f, sb = 0.f;
#pragma unroll
        for (int nt = 0; nt < 8; nt++) {
            S[nt][0] = __expf(S[nt][0] - mn_a);
            S[nt][1] = __expf(S[nt][1] - mn_a);
            S[nt][2] = __expf(S[nt][2] - mn_b);
            S[nt][3] = __expf(S[nt][3] - mn_b);
            sa += S[nt][0] + S[nt][1];
            sb += S[nt][2] + S[nt][3];
        }
#pragma unroll
        for (int d = 1; d <= 2; d <<= 1) {
            sa += __shfl_xor_sync(0xffffffffu, sa, d);
            sb += __shfl_xor_sync(0xffffffffu, sb, d);
        }
        l_a = l_a * sf_a + sa;
        l_b = l_b * sf_b + sb;
#pragma unroll
        for (int nt = 0; nt < 4; nt++) {
            out[nt][0] *= sf_a; out[nt][1] *= sf_a;
            out[nt][2] *= sf_b; out[nt][3] *= sf_b;
        }

        // ---- out += P @ V (3xTF32). A-frags = S-frags directly:
        //   a0=S[kt][0](row g,2tig), a1=S[kt][2](row g+8,2tig),
        //   a2=S[kt][1](row g,2tig+1), a3=S[kt][3](row g+8,2tig+1);
        //   valid because Vp rows are even/odd-permuted per 8-group.
#pragma unroll
        for (int kt = 0; kt < 8; kt++) {
            u32 ah[4], al[4];
            split_tf32(S[kt][0], ah[0], al[0]);
            split_tf32(S[kt][2], ah[1], al[1]);
            split_tf32(S[kt][1], ah[2], al[2]);
            split_tf32(S[kt][3], ah[3], al[3]);
#pragma unroll
            for (int nt = 0; nt < 4; nt++) {
                u32 bh0, bl0, bh1, bl1;
                split_tf32(Vp[kt * 8 + tig][nt * 8 + g],     bh0, bl0);
                split_tf32(Vp[kt * 8 + tig + 4][nt * 8 + g], bh1, bl1);
                mma3(out[nt], ah, al, bh0, bh1, bl0, bl1);
            }
        }
        __syncthreads();   // before next chunk overwrites Ks/Vp
    }

    const float inv_a = 1.0f / l_a;
    const float inv_b = 1.0f / l_b;
    const int ra = q0 + 16 * w + g;
    const int rb = ra + 8;
#pragma unroll
    for (int nt = 0; nt < 4; nt++) {
        int d = nt * 8 + 2 * tig;
        if (ra < qe) {
            float* p = g_att + (size_t)ra * E_DIM + h * HDIM + d;
            p[0] = out[nt][0] * inv_a;
            p[1] = out[nt][1] * inv_a;
        }
        if (rb < qe) {
            float* p = g_att + (size_t)rb * E_DIM + h * HDIM + d;
            p[0] = out[nt][2] * inv_b;
            p[1] = out[nt][3] * inv_b;
        }
    }
}

// ---------------------------------------------------------------------------
extern "C" void kernel_launch(void* const* d_in, const int* in_sizes, int n_in,
                              void* d_out, int out_size) {
    const float* x      = (const float*)d_in[0];
    const int*   ids    = (const int*)  d_in[1];
    const float* qkv_w  = (const float*)d_in[2];
    const float* qkv_b  = (const float*)d_in[3];
    const float* o_w    = (const float*)d_in[4];
    const float* o_b    = (const float*)d_in[5];
    float*       out    = (float*)d_out;
    const int n = in_sizes[1];   // token count

    hist_kernel<<<1, 256>>>(ids, n);

    float* qkv_out = nullptr;
    cudaGetSymbolAddress((void**)&qkv_out, g_qkv);
    float* att_out = nullptr;
    cudaGetSymbolAddress((void**)&att_out, g_att);

    dim3 g_qkv_grid(QKV_DIM / 64, (n + 63) / 64);
    mma_gemm_kernel<<<g_qkv_grid, 128>>>(x, qkv_w, qkv_b, qkv_out, n, QKV_DIM, IN_DIM);

    dim3 g_attn((n + 63) / 64, NB, NHEAD);
    attn_mma_kernel<<<g_attn, 128>>>(n);

    dim3 g_proj(E_DIM / 64, (n + 63) / 64);
    mma_gemm_kernel<<<g_proj, 128>>>(att_out, o_w, o_b, out, n, E_DIM, E_DIM);
}